// round 7
// baseline (speedup 1.0000x reference)
#include <cuda_runtime.h>

#define B_   64
#define T_   512
#define D_   256
#define U_   512
#define G3   1536
#define NBLK 64
#define NTHR 512
#define SCAN_SMEM 65536   // 64KB dynamic

// ---------------- device scratch (no allocations allowed) ----------------
__device__ float g_gx[(size_t)2 * T_ * B_ * G3];   // [dir][t][b][3U] gate preacts
__device__ float g_h [2 * B_ * U_];
__device__ float g_u [2 * B_ * U_];
__device__ float g_rh[2 * B_ * U_];
// split arrive/wait barrier slots: 0=fA 1=bA 2=fB 3=bB (monotone per launch)
__device__ unsigned g_cnt[4] = {0, 0, 0, 0};
// self-resetting gen barrier (init + pre-reset fence)
__device__ unsigned          g_genc = 0;
__device__ volatile unsigned g_geng = 0;

__device__ __forceinline__ void full_barrier() {
    __threadfence();
    __syncthreads();
    if (threadIdx.x == 0) {
        unsigned g = g_geng;
        unsigned prev = atomicAdd(&g_genc, 1u);
        if (prev == NBLK - 1) {
            g_genc = 0u;
            __threadfence();
            g_geng = g + 1u;
        } else {
            while (g_geng == g) { }
        }
    }
    __syncthreads();
}

__device__ __forceinline__ void bar_arrive(int s) {
    __syncthreads();                       // all threads' stores done
    if (threadIdx.x == 0) {
        __threadfence();                   // make them globally visible first
        atomicAdd(&g_cnt[s], 1u);
    }
}
__device__ __forceinline__ void bar_wait(int s, unsigned target) {
    if (threadIdx.x == 0) {
        unsigned v;
        do { v = *(volatile unsigned*)&g_cnt[s]; } while ((int)(v - target) < 0);
    }
    __syncthreads();
}

__device__ __forceinline__ float sigmoidf_(float z) {
    return 1.0f / (1.0f + __expf(-z));
}

// ---------------- packed f32x2 helpers ----------------
__device__ __forceinline__ void ffma2(unsigned long long& d,
                                      unsigned long long a,
                                      unsigned long long b) {
    asm("fma.rn.f32x2 %0, %1, %2, %0;" : "+l"(d) : "l"(a), "l"(b));
}
__device__ __forceinline__ unsigned long long dup2(float x) {
    unsigned long long r; unsigned u = __float_as_uint(x);
    asm("mov.b64 %0, {%1, %1};" : "=l"(r) : "r"(u));
    return r;
}
__device__ __forceinline__ float2 up2(unsigned long long v) {
    float2 f;
    asm("mov.b64 {%0, %1}, %2;" : "=f"(f.x), "=f"(f.y) : "l"(v));
    return f;
}

// =====================================================================
// Kernel A: input projections for BOTH directions (FFMA2 GEMM).
// =====================================================================
__global__ void __launch_bounds__(256) k_inproj(
    const float* __restrict__ x,
    const float* __restrict__ Wxf,
    const float* __restrict__ Wxb)
{
    __shared__ __align__(16) float As[16 * 64];
    __shared__ __align__(16) float Bs[16 * 64];

    const int tid = threadIdx.x;
    const int m0  = blockIdx.x * 64;
    const int n0g = blockIdx.y * 64;
    const int dir = (n0g >= G3) ? 1 : 0;
    const float* __restrict__ W = dir ? Wxb : Wxf;
    const int n0 = n0g - dir * G3;

    const int bg = tid >> 4;
    const int ng = tid & 15;
    const int ar = tid >> 2, aq = tid & 3;
    const int bk = tid >> 4, bc = tid & 15;

    unsigned long long acc[2][4];
#pragma unroll
    for (int p = 0; p < 2; p++)
#pragma unroll
        for (int j = 0; j < 4; j++) acc[p][j] = 0ull;

    for (int k0 = 0; k0 < D_; k0 += 16) {
        float4 av = *reinterpret_cast<const float4*>(x + (size_t)(m0 + ar) * D_ + k0 + aq * 4);
        float4 bv = *reinterpret_cast<const float4*>(W + (size_t)(k0 + bk) * G3 + n0 + bc * 4);
        __syncthreads();
        As[(aq * 4 + 0) * 64 + ar] = av.x;
        As[(aq * 4 + 1) * 64 + ar] = av.y;
        As[(aq * 4 + 2) * 64 + ar] = av.z;
        As[(aq * 4 + 3) * 64 + ar] = av.w;
        *reinterpret_cast<float4*>(&Bs[bk * 64 + bc * 4]) = bv;
        __syncthreads();
#pragma unroll
        for (int kk = 0; kk < 16; kk++) {
            ulonglong2 a2 = *reinterpret_cast<const ulonglong2*>(&As[kk * 64 + bg * 4]);
            float4 b4 = *reinterpret_cast<const float4*>(&Bs[kk * 64 + ng * 4]);
            unsigned long long w0 = dup2(b4.x), w1 = dup2(b4.y),
                               w2 = dup2(b4.z), w3 = dup2(b4.w);
            ffma2(acc[0][0], a2.x, w0); ffma2(acc[0][1], a2.x, w1);
            ffma2(acc[0][2], a2.x, w2); ffma2(acc[0][3], a2.x, w3);
            ffma2(acc[1][0], a2.y, w0); ffma2(acc[1][1], a2.y, w1);
            ffma2(acc[1][2], a2.y, w2); ffma2(acc[1][3], a2.y, w3);
        }
    }

    float accf[4][4];
#pragma unroll
    for (int p = 0; p < 2; p++)
#pragma unroll
        for (int j = 0; j < 4; j++) {
            float2 f = up2(acc[p][j]);
            accf[2 * p][j]     = f.x;
            accf[2 * p + 1][j] = f.y;
        }

#pragma unroll
    for (int i = 0; i < 4; i++) {
        int m = m0 + bg * 4 + i;
        int b = m >> 9;
        int s = m & 511;
        int t = dir ? (T_ - 1 - s) : s;
        float* dst = g_gx + (((size_t)dir * T_ + t) * B_ + b) * G3 + n0 + ng * 4;
        *reinterpret_cast<float4*>(dst) =
            make_float4(accf[i][0], accf[i][1], accf[i][2], accf[i][3]);
    }
}

// =====================================================================
// Kernel B: persistent scan, 64 blocks x 512 thr, BOTH dirs per block,
// software-pipelined so each barrier wait hides under the other
// direction's compute. FFMA2 micro-tiles, chunked staging.
// =====================================================================
extern __shared__ float s_u[];

__global__ void __launch_bounds__(NTHR, 1) k_scan(
    const float* __restrict__ Whf, const float* __restrict__ Whb,
    const float* __restrict__ bf,  const float* __restrict__ bb,
    float* __restrict__ out)
{
    const int tid = threadIdx.x;
    const int blk = blockIdx.x;          // 0..63

    const int cbaseA = blk * 16;         // cols in [0,1024)
    const int cbaseB = blk * 8;          // cols in [0,512)

    float* hF  = g_h;             float* hB  = g_h  + B_ * U_;
    float* uF  = g_u;             float* uB  = g_u  + B_ * U_;
    float* rhF = g_rh;            float* rhB = g_rh + B_ * U_;
    const float* gxF = g_gx;
    const float* gxB = g_gx + (size_t)T_ * B_ * G3;

    // ---- Phase A mapping: 16 kg (1 warp each), K=32; micro 8b x 4c
    const int kgA = tid >> 5;
    const int tA  = tid & 31;
    const int b0A = (tA >> 2) << 3;
    const int c0A = (tA & 3) << 2;
    const int kbA = kgA << 5;
    const int qA  = tA & 1;
    const int blA = tA >> 1;
    const int stA = kgA << 9;            // 512-float staging region per kg
    const int oidA = tid << 1;
    const int bA0 = oidA >> 4;           // same row for both outputs
    const int cA0 = oidA & 15;           // even
    const int cgA0 = cbaseA + cA0, cgA1 = cgA0 + 1;
    const int swA  = (bA0 >> 2) & 14;    // reduction-layout swizzle mask

    // ---- Phase B mapping: 32 kg (half-warp each), K=16; micro 8b x 4c
    const int kgB = tid >> 4;
    const int tB  = tid & 15;
    const int b0B = (tB >> 1) << 3;
    const int c0B = (tB & 1) << 2;
    const int kbB = kgB << 4;
    const int stB = kgB << 8;            // 256-float staging region per kg
    const int bB  = tid >> 3;
    const int cB  = tid & 7;
    const int cgB = cbaseB + cB;
    const int rdB = (bB << 3) + ((cB + (bB >> 3)) & 7);   // swizzled read idx

    const float bAf0 = __ldg(bf + cgA0), bAf1 = __ldg(bf + cgA1);
    const float bAb0 = __ldg(bb + cgA0), bAb1 = __ldg(bb + cgA1);
    const float bBf  = __ldg(bf + 1024 + cgB);
    const float bBb  = __ldg(bb + 1024 + cgB);

    // zero h (65536 floats over 32768 threads -> 2 each)
    {
        int idx = blk * NTHR + tid;
        __stcg(&g_h[idx], 0.0f);
        __stcg(&g_h[idx + 32768], 0.0f);
    }
    full_barrier();

    // ---------------- phase A (u,r gates) ----------------
    auto phaseA = [&](const float* __restrict__ hb, float* ub, float* rhb,
                      const float* __restrict__ Whp, const float* __restrict__ gxt,
                      float bias0, float bias1) {
        float gxa0 = __ldg(gxt + (size_t)bA0 * G3 + cgA0);
        float gxa1 = __ldg(gxt + (size_t)bA0 * G3 + cgA1);

        float4 pf[4];
#pragma unroll
        for (int j = 0; j < 4; j++)
            pf[j] = __ldcg(reinterpret_cast<const float4*>(
                hb + (size_t)(blA + j * 16) * U_ + kbA + qA * 4));

        unsigned long long acc[4][4];
#pragma unroll
        for (int p = 0; p < 4; p++)
#pragma unroll
            for (int j = 0; j < 4; j++) acc[p][j] = 0ull;

        for (int ch = 0; ch < 4; ch++) {
            const int k0 = kbA + ch * 8;
            __syncthreads();
#pragma unroll
            for (int j = 0; j < 4; j++) {
                int base = stA + (qA * 4) * 64 + blA + j * 16;
                s_u[base]       = pf[j].x;
                s_u[base + 64]  = pf[j].y;
                s_u[base + 128] = pf[j].z;
                s_u[base + 192] = pf[j].w;
            }
            __syncthreads();
            if (ch < 3) {
#pragma unroll
                for (int j = 0; j < 4; j++)
                    pf[j] = __ldcg(reinterpret_cast<const float4*>(
                        hb + (size_t)(blA + j * 16) * U_ + k0 + 8 + qA * 4));
            }
            const float* sp = s_u + stA + b0A;
#pragma unroll
            for (int kk = 0; kk < 8; kk++) {
                ulonglong2 a01 = *reinterpret_cast<const ulonglong2*>(sp + kk * 64);
                ulonglong2 a23 = *reinterpret_cast<const ulonglong2*>(sp + kk * 64 + 4);
                float4 w4 = __ldg(reinterpret_cast<const float4*>(
                    Whp + (size_t)(k0 + kk) * G3 + cbaseA + c0A));
                unsigned long long w0 = dup2(w4.x), w1 = dup2(w4.y),
                                   w2 = dup2(w4.z), w3 = dup2(w4.w);
                ffma2(acc[0][0], a01.x, w0); ffma2(acc[0][1], a01.x, w1);
                ffma2(acc[0][2], a01.x, w2); ffma2(acc[0][3], a01.x, w3);
                ffma2(acc[1][0], a01.y, w0); ffma2(acc[1][1], a01.y, w1);
                ffma2(acc[1][2], a01.y, w2); ffma2(acc[1][3], a01.y, w3);
                ffma2(acc[2][0], a23.x, w0); ffma2(acc[2][1], a23.x, w1);
                ffma2(acc[2][2], a23.x, w2); ffma2(acc[2][3], a23.x, w3);
                ffma2(acc[3][0], a23.y, w0); ffma2(acc[3][1], a23.y, w1);
                ffma2(acc[3][2], a23.y, w2); ffma2(acc[3][3], a23.y, w3);
            }
        }
        __syncthreads();
#pragma unroll
        for (int p = 0; p < 4; p++)
#pragma unroll
            for (int j = 0; j < 4; j++) {
                float2 f = up2(acc[p][j]);
                int r0 = b0A + 2 * p;
                int m0m = (r0 >> 2) & 14;         // same for r0 and r0+1
                s_u[(kgA << 10) + r0 * 16 + ((c0A + j) ^ m0m)]       = f.x;
                s_u[(kgA << 10) + (r0 + 1) * 16 + ((c0A + j) ^ m0m)] = f.y;
            }
        __syncthreads();

        float z0 = 0.0f, z1 = 0.0f;
        const int rbase = bA0 * 16 + (cA0 ^ swA);
#pragma unroll
        for (int kg = 0; kg < 16; kg++) {
            float2 v = *reinterpret_cast<const float2*>(&s_u[(kg << 10) + rbase]);
            z0 += v.x; z1 += v.y;
        }
        float sg0 = sigmoidf_(z0 + gxa0 + bias0);
        float sg1 = sigmoidf_(z1 + gxa1 + bias1);
        if (cgA0 < U_) {
            __stcg(ub + bA0 * U_ + cgA0, sg0);
            __stcg(ub + bA0 * U_ + cgA1, sg1);
        } else {
            float h0 = __ldcg(hb + bA0 * U_ + cgA0 - U_);
            float h1 = __ldcg(hb + bA0 * U_ + cgA1 - U_);
            __stcg(rhb + bA0 * U_ + cgA0 - U_, sg0 * h0);
            __stcg(rhb + bA0 * U_ + cgA1 - U_, sg1 * h1);
        }
    };

    // ---------------- phase B (candidate + blend) ----------------
    auto phaseB = [&](float* hb, const float* __restrict__ ub,
                      const float* __restrict__ rhb,
                      const float* __restrict__ Whp, const float* __restrict__ gxt,
                      float biasc, int dir, int t) {
        float gxb = __ldg(gxt + (size_t)bB * G3 + 1024 + cgB);

        float4 pf[4];
#pragma unroll
        for (int j = 0; j < 4; j++)
            pf[j] = __ldcg(reinterpret_cast<const float4*>(
                rhb + (size_t)(tB + j * 16) * U_ + kbB));

        unsigned long long acc[4][4];
#pragma unroll
        for (int p = 0; p < 4; p++)
#pragma unroll
            for (int j = 0; j < 4; j++) acc[p][j] = 0ull;

        for (int ch = 0; ch < 4; ch++) {
            const int k0 = kbB + ch * 4;
            __syncthreads();
#pragma unroll
            for (int j = 0; j < 4; j++) {
                int base = stB + tB + j * 16;
                s_u[base]       = pf[j].x;
                s_u[base + 64]  = pf[j].y;
                s_u[base + 128] = pf[j].z;
                s_u[base + 192] = pf[j].w;
            }
            __syncthreads();
            if (ch < 3) {
#pragma unroll
                for (int j = 0; j < 4; j++)
                    pf[j] = __ldcg(reinterpret_cast<const float4*>(
                        rhb + (size_t)(tB + j * 16) * U_ + k0 + 4));
            }
            const float* sp = s_u + stB + b0B;
#pragma unroll
            for (int kk = 0; kk < 4; kk++) {
                ulonglong2 a01 = *reinterpret_cast<const ulonglong2*>(sp + kk * 64);
                ulonglong2 a23 = *reinterpret_cast<const ulonglong2*>(sp + kk * 64 + 4);
                float4 w4 = __ldg(reinterpret_cast<const float4*>(
                    Whp + (size_t)(k0 + kk) * G3 + 1024 + cbaseB + c0B));
                unsigned long long w0 = dup2(w4.x), w1 = dup2(w4.y),
                                   w2 = dup2(w4.z), w3 = dup2(w4.w);
                ffma2(acc[0][0], a01.x, w0); ffma2(acc[0][1], a01.x, w1);
                ffma2(acc[0][2], a01.x, w2); ffma2(acc[0][3], a01.x, w3);
                ffma2(acc[1][0], a01.y, w0); ffma2(acc[1][1], a01.y, w1);
                ffma2(acc[1][2], a01.y, w2); ffma2(acc[1][3], a01.y, w3);
                ffma2(acc[2][0], a23.x, w0); ffma2(acc[2][1], a23.x, w1);
                ffma2(acc[2][2], a23.x, w2); ffma2(acc[2][3], a23.x, w3);
                ffma2(acc[3][0], a23.y, w0); ffma2(acc[3][1], a23.y, w1);
                ffma2(acc[3][2], a23.y, w2); ffma2(acc[3][3], a23.y, w3);
            }
        }
        __syncthreads();
#pragma unroll
        for (int p = 0; p < 4; p++)
#pragma unroll
            for (int j = 0; j < 4; j++) {
                float2 f = up2(acc[p][j]);
                int r0 = b0B + 2 * p;
                int off0 = (c0B + j + (r0 >> 3)) & 7;   // r0,r0+1 share >>3
                s_u[(kgB << 9) + r0 * 8 + off0]       = f.x;
                s_u[(kgB << 9) + (r0 + 1) * 8 + off0] = f.y;
            }
        __syncthreads();

        float z = 0.0f;
#pragma unroll
        for (int kg = 0; kg < 32; kg++) z += s_u[(kg << 9) + rdB];
        float hh   = tanhf(z + gxb + biasc);
        float uu   = __ldcg(ub + bB * U_ + cgB);
        float hold = __ldcg(hb + bB * U_ + cgB);
        float hnew = hold + uu * (hh - hold);
        __stcg(hb + bB * U_ + cgB, hnew);
        out[((size_t)bB * T_ + t) * 1024 + dir * U_ + cgB] = hnew;
    };

    // ---------------- time loop, dual-direction pipelined ----------------
    for (int t = 0; t < T_; t++) {
        const float* gxtF = gxF + (size_t)t * B_ * G3;
        const float* gxtB = gxB + (size_t)t * B_ * G3;
        const unsigned tp = 64u * (unsigned)t;
        const unsigned tc = tp + 64u;

        if (t) bar_wait(2, tp);                       // fB of step t-1
        phaseA(hF, uF, rhF, Whf, gxtF, bAf0, bAf1);
        bar_arrive(0);                                // fA
        if (t) bar_wait(3, tp);                       // bB of step t-1
        phaseA(hB, uB, rhB, Whb, gxtB, bAb0, bAb1);
        bar_arrive(1);                                // bA
        bar_wait(0, tc);                              // fA complete
        phaseB(hF, uF, rhF, Whf, gxtF, bBf, 0, t);
        bar_arrive(2);                                // fB
        bar_wait(1, tc);                              // bA complete
        phaseB(hB, uB, rhB, Whb, gxtB, bBb, 1, t);
        bar_arrive(3);                                // bB
    }

    // reset monotone counters for the next graph replay
    full_barrier();
    if (blk == 0 && tid == 0) {
        g_cnt[0] = 0; g_cnt[1] = 0; g_cnt[2] = 0; g_cnt[3] = 0;
    }
}

// =====================================================================
extern "C" void kernel_launch(void* const* d_in, const int* in_sizes, int n_in,
                              void* d_out, int out_size)
{
    const float* x   = (const float*)d_in[0];
    const float* Wxf = (const float*)d_in[1];
    const float* Whf = (const float*)d_in[2];
    const float* bf  = (const float*)d_in[3];
    const float* Wxb = (const float*)d_in[4];
    const float* Whb = (const float*)d_in[5];
    const float* bb  = (const float*)d_in[6];
    float* out = (float*)d_out;

    cudaFuncSetAttribute(k_scan, cudaFuncAttributeMaxDynamicSharedMemorySize, SCAN_SMEM);

    dim3 gA(512, 48);
    k_inproj<<<gA, 256>>>(x, Wxf, Wxb);
    k_scan<<<NBLK, NTHR, SCAN_SMEM>>>(Whf, Whb, bf, bb, out);
}

// round 8
// speedup vs baseline: 1.6614x; 1.6614x over previous
#include <cuda_runtime.h>

#define B_   64
#define T_   512
#define D_   256
#define U_   512
#define G3   1536
#define CLUSTER 16
#define NBLK 128
#define NTHR 512
#define SCAN_SMEM 229376   // Wa 128KB + hbuf 32KB + partials 64KB

// ---------------- device scratch (no allocations allowed) ----------------
__device__ float g_gx[(size_t)2 * T_ * B_ * G3];   // [dir][t][b][3U]
// per (dir,bgroup) transposed state: [sid][ucol 512][b 16]
__device__ float g_hT [8 * U_ * 16];
__device__ float g_rhT[8 * U_ * 16];
__device__ float g_uT [8 * U_ * 16];

__device__ __forceinline__ float sigmoidf_(float z) {
    return 1.0f / (1.0f + __expf(-z));
}
__device__ __forceinline__ void ffma2(unsigned long long& d,
                                      unsigned long long a,
                                      unsigned long long b) {
    asm("fma.rn.f32x2 %0, %1, %2, %0;" : "+l"(d) : "l"(a), "l"(b));
}
__device__ __forceinline__ unsigned long long dup2(float x) {
    unsigned long long r; unsigned u = __float_as_uint(x);
    asm("mov.b64 %0, {%1, %1};" : "=l"(r) : "r"(u));
    return r;
}
__device__ __forceinline__ float2 up2(unsigned long long v) {
    float2 f;
    asm("mov.b64 {%0, %1}, %2;" : "=f"(f.x), "=f"(f.y) : "l"(v));
    return f;
}
__device__ __forceinline__ void cluster_sync_() {
    asm volatile("barrier.cluster.arrive.aligned;" ::: "memory");
    asm volatile("barrier.cluster.wait.aligned;" ::: "memory");
}

// =====================================================================
// Kernel A: input projections for BOTH directions (FFMA2 GEMM).
// =====================================================================
__global__ void __launch_bounds__(256) k_inproj(
    const float* __restrict__ x,
    const float* __restrict__ Wxf,
    const float* __restrict__ Wxb)
{
    __shared__ __align__(16) float As[16 * 64];
    __shared__ __align__(16) float Bs[16 * 64];

    const int tid = threadIdx.x;
    const int m0  = blockIdx.x * 64;
    const int n0g = blockIdx.y * 64;
    const int dir = (n0g >= G3) ? 1 : 0;
    const float* __restrict__ W = dir ? Wxb : Wxf;
    const int n0 = n0g - dir * G3;

    const int bg = tid >> 4;
    const int ng = tid & 15;
    const int ar = tid >> 2, aq = tid & 3;
    const int bk = tid >> 4, bc = tid & 15;

    unsigned long long acc[2][4];
#pragma unroll
    for (int p = 0; p < 2; p++)
#pragma unroll
        for (int j = 0; j < 4; j++) acc[p][j] = 0ull;

    for (int k0 = 0; k0 < D_; k0 += 16) {
        float4 av = *reinterpret_cast<const float4*>(x + (size_t)(m0 + ar) * D_ + k0 + aq * 4);
        float4 bv = *reinterpret_cast<const float4*>(W + (size_t)(k0 + bk) * G3 + n0 + bc * 4);
        __syncthreads();
        As[(aq * 4 + 0) * 64 + ar] = av.x;
        As[(aq * 4 + 1) * 64 + ar] = av.y;
        As[(aq * 4 + 2) * 64 + ar] = av.z;
        As[(aq * 4 + 3) * 64 + ar] = av.w;
        *reinterpret_cast<float4*>(&Bs[bk * 64 + bc * 4]) = bv;
        __syncthreads();
#pragma unroll
        for (int kk = 0; kk < 16; kk++) {
            ulonglong2 a2 = *reinterpret_cast<const ulonglong2*>(&As[kk * 64 + bg * 4]);
            float4 b4 = *reinterpret_cast<const float4*>(&Bs[kk * 64 + ng * 4]);
            unsigned long long w0 = dup2(b4.x), w1 = dup2(b4.y),
                               w2 = dup2(b4.z), w3 = dup2(b4.w);
            ffma2(acc[0][0], a2.x, w0); ffma2(acc[0][1], a2.x, w1);
            ffma2(acc[0][2], a2.x, w2); ffma2(acc[0][3], a2.x, w3);
            ffma2(acc[1][0], a2.y, w0); ffma2(acc[1][1], a2.y, w1);
            ffma2(acc[1][2], a2.y, w2); ffma2(acc[1][3], a2.y, w3);
        }
    }

    float accf[4][4];
#pragma unroll
    for (int p = 0; p < 2; p++)
#pragma unroll
        for (int j = 0; j < 4; j++) {
            float2 f = up2(acc[p][j]);
            accf[2 * p][j]     = f.x;
            accf[2 * p + 1][j] = f.y;
        }

#pragma unroll
    for (int i = 0; i < 4; i++) {
        int m = m0 + bg * 4 + i;
        int b = m >> 9;
        int s = m & 511;
        int t = dir ? (T_ - 1 - s) : s;
        float* dst = g_gx + (((size_t)dir * T_ + t) * B_ + b) * G3 + n0 + ng * 4;
        *reinterpret_cast<float4*>(dst) =
            make_float4(accf[i][0], accf[i][1], accf[i][2], accf[i][3]);
    }
}

// =====================================================================
// Kernel B: cluster-local BiGRU scan. 8 clusters x 16 CTAs, no grid
// barriers. Cluster = (dir, batch-group of 16). Per CTA:
//   phase A: 64 of 1024 u/r cols, Wa resident in smem.
//   phase B: 32 of 512 cand cols, Wb streamed from L2.
// State h / r*h / u in transposed [col][16b] global buffers, exchanged
// via L2 + barrier.cluster (release/acquire).
// =====================================================================
extern __shared__ float smem_[];

__global__ void __launch_bounds__(NTHR, 1) __cluster_dims__(CLUSTER, 1, 1)
k_scan(const float* __restrict__ Whf, const float* __restrict__ Whb,
       const float* __restrict__ bf,  const float* __restrict__ bb,
       float* __restrict__ out)
{
    float* Wa   = smem_;                 // [512][64]   32768 floats
    float* hbuf = smem_ + 32768;         // [512][16]    8192 floats
    float* part = smem_ + 40960;         // [16][1024]  16384 floats

    const int tid  = threadIdx.x;
    const int blk  = blockIdx.x;
    const int cid  = blk >> 4;           // cluster id 0..7
    const int rank = blk & 15;           // CTA rank in cluster
    const int dir  = cid >> 2;
    const int bg   = cid & 3;

    const float* __restrict__ Wh   = dir ? Whb : Whf;
    const float* __restrict__ bias = dir ? bb : bf;
    float* hT  = g_hT  + cid * (U_ * 16);
    float* rhT = g_rhT + cid * (U_ * 16);
    float* uT  = g_uT  + cid * (U_ * 16);

    // ---- load Wa slice (phase-A cols [rank*64, +64)) into smem ----
    for (int i = tid; i < 8192; i += NTHR) {
        int k = i >> 4, cc = (i & 15) << 2;
        *reinterpret_cast<float4*>(Wa + k * 64 + cc) =
            __ldg(reinterpret_cast<const float4*>(Wh + (size_t)k * G3 + rank * 64 + cc));
    }

    // ---- phase A mapping: 16 kg x 32 thr, K=32; micro 8b x 4c ----
    const int kgA = tid >> 5;
    const int tA  = tid & 31;
    const int b0A = (tA & 1) << 3;
    const int c0A = (tA >> 1) << 2;
    const int kbA = kgA << 5;
    const int oidA = tid << 1;            // outputs (b, cA), (b, cA+1)
    const int bA  = oidA >> 6;
    const int cA  = oidA & 63;            // even
    const int cgA = rank * 64 + cA;       // global col in [0,1024)
    const float biasA0 = __ldg(bias + cgA);
    const float biasA1 = __ldg(bias + cgA + 1);
    const bool isU = (rank < 8);
    const int rcolA = cgA - U_;           // valid when !isU

    // ---- phase B mapping: 16 kg x 32 thr, K=32; micro 8b x 2c ----
    const int b0B = (tA & 1) << 3;
    const int c0B = (tA >> 1) << 1;
    const int bB  = tid >> 5;             // output (bB, cB)
    const int cB  = tid & 31;
    const int colB = rank * 32 + cB;      // global cand col in [0,512)
    const float biasB = __ldg(bias + 1024 + colB);
    const float* WbBase = Wh + 1024 + rank * 32 + c0B;

    for (int t = 0; t < T_; t++) {
        const float* gxt = g_gx + ((size_t)dir * T_ + t) * (B_ * G3)
                         + (size_t)bg * 16 * G3;

        // ---- stage h^T into smem ----
        if (t == 0) {
            for (int i = tid; i < 8192; i += NTHR) hbuf[i] = 0.0f;
        } else {
            for (int i = tid; i < 2048; i += NTHR)
                *reinterpret_cast<float4*>(hbuf + i * 4) =
                    __ldcg(reinterpret_cast<const float4*>(hT + i * 4));
        }
        float2 gxa = __ldg(reinterpret_cast<const float2*>(
            gxt + (size_t)bA * G3 + cgA));
        __syncthreads();

        // ---- phase A GEMM: z = h @ Wa (16b x 64c, K=512 split 16) ----
        {
            unsigned long long acc[4][4];
#pragma unroll
            for (int p = 0; p < 4; p++)
#pragma unroll
                for (int j = 0; j < 4; j++) acc[p][j] = 0ull;

#pragma unroll 8
            for (int k = 0; k < 32; k++) {
                const float* hp = hbuf + (kbA + k) * 16 + b0A;
                ulonglong2 a01 = *reinterpret_cast<const ulonglong2*>(hp);
                ulonglong2 a23 = *reinterpret_cast<const ulonglong2*>(hp + 4);
                float4 w4 = *reinterpret_cast<const float4*>(Wa + (kbA + k) * 64 + c0A);
                unsigned long long w0 = dup2(w4.x), w1 = dup2(w4.y),
                                   w2 = dup2(w4.z), w3 = dup2(w4.w);
                ffma2(acc[0][0], a01.x, w0); ffma2(acc[0][1], a01.x, w1);
                ffma2(acc[0][2], a01.x, w2); ffma2(acc[0][3], a01.x, w3);
                ffma2(acc[1][0], a01.y, w0); ffma2(acc[1][1], a01.y, w1);
                ffma2(acc[1][2], a01.y, w2); ffma2(acc[1][3], a01.y, w3);
                ffma2(acc[2][0], a23.x, w0); ffma2(acc[2][1], a23.x, w1);
                ffma2(acc[2][2], a23.x, w2); ffma2(acc[2][3], a23.x, w3);
                ffma2(acc[3][0], a23.y, w0); ffma2(acc[3][1], a23.y, w1);
                ffma2(acc[3][2], a23.y, w2); ffma2(acc[3][3], a23.y, w3);
            }
#pragma unroll
            for (int p = 0; p < 4; p++)
#pragma unroll
                for (int j = 0; j < 4; j++) {
                    float2 f = up2(acc[p][j]);
                    int r0 = b0A + 2 * p;
                    part[kgA * 1024 + r0 * 64 + c0A + j]       = f.x;
                    part[kgA * 1024 + (r0 + 1) * 64 + c0A + j] = f.y;
                }
        }
        __syncthreads();
        {
            float z0 = 0.0f, z1 = 0.0f;
#pragma unroll
            for (int kg = 0; kg < 16; kg++) {
                float2 v = *reinterpret_cast<const float2*>(part + kg * 1024 + oidA);
                z0 += v.x; z1 += v.y;
            }
            float s0 = sigmoidf_(z0 + gxa.x + biasA0);
            float s1 = sigmoidf_(z1 + gxa.y + biasA1);
            if (isU) {
                __stcg(uT + cgA * 16 + bA, s0);
                __stcg(uT + (cgA + 1) * 16 + bA, s1);
            } else {
                __stcg(rhT + rcolA * 16 + bA, s0 * hbuf[rcolA * 16 + bA]);
                __stcg(rhT + (rcolA + 1) * 16 + bA, s1 * hbuf[(rcolA + 1) * 16 + bA]);
            }
        }
        cluster_sync_();   // u, r*h visible cluster-wide

        // ---- phase B prologue: grab h_old/u for own cols, then swap ----
        float hold = hbuf[colB * 16 + bB];
        float uval = __ldcg(uT + colB * 16 + bB);
        float gxb  = __ldg(gxt + (size_t)bB * G3 + 1024 + colB);
        __syncthreads();
        for (int i = tid; i < 2048; i += NTHR)
            *reinterpret_cast<float4*>(hbuf + i * 4) =
                __ldcg(reinterpret_cast<const float4*>(rhT + i * 4));
        __syncthreads();

        // ---- phase B GEMM: c = (r*h) @ Wb (16b x 32c, K=512 split 16) ----
        {
            unsigned long long acc[4][2];
#pragma unroll
            for (int p = 0; p < 4; p++) { acc[p][0] = 0ull; acc[p][1] = 0ull; }

#pragma unroll 8
            for (int k = 0; k < 32; k++) {
                const float* hp = hbuf + (kbA + k) * 16 + b0B;
                ulonglong2 a01 = *reinterpret_cast<const ulonglong2*>(hp);
                ulonglong2 a23 = *reinterpret_cast<const ulonglong2*>(hp + 4);
                float2 w2 = __ldg(reinterpret_cast<const float2*>(
                    WbBase + (size_t)(kbA + k) * G3));
                unsigned long long w0 = dup2(w2.x), w1 = dup2(w2.y);
                ffma2(acc[0][0], a01.x, w0); ffma2(acc[0][1], a01.x, w1);
                ffma2(acc[1][0], a01.y, w0); ffma2(acc[1][1], a01.y, w1);
                ffma2(acc[2][0], a23.x, w0); ffma2(acc[2][1], a23.x, w1);
                ffma2(acc[3][0], a23.y, w0); ffma2(acc[3][1], a23.y, w1);
            }
#pragma unroll
            for (int p = 0; p < 4; p++)
#pragma unroll
                for (int j = 0; j < 2; j++) {
                    float2 f = up2(acc[p][j]);
                    int r0 = b0B + 2 * p;
                    part[kgA * 512 + r0 * 32 + c0B + j]       = f.x;
                    part[kgA * 512 + (r0 + 1) * 32 + c0B + j] = f.y;
                }
        }
        __syncthreads();
        {
            float z = 0.0f;
#pragma unroll
            for (int kg = 0; kg < 16; kg++) z += part[kg * 512 + tid];
            float hh   = tanhf(z + gxb + biasB);
            float hnew = hold + uval * (hh - hold);
            __stcg(hT + colB * 16 + bB, hnew);
            out[((size_t)(bg * 16 + bB) * T_ + t) * 1024 + dir * U_ + colB] = hnew;
        }
        cluster_sync_();   // h_new visible before next step's stage
    }
}

// =====================================================================
extern "C" void kernel_launch(void* const* d_in, const int* in_sizes, int n_in,
                              void* d_out, int out_size)
{
    const float* x   = (const float*)d_in[0];
    const float* Wxf = (const float*)d_in[1];
    const float* Whf = (const float*)d_in[2];
    const float* bf  = (const float*)d_in[3];
    const float* Wxb = (const float*)d_in[4];
    const float* Whb = (const float*)d_in[5];
    const float* bb  = (const float*)d_in[6];
    float* out = (float*)d_out;

    // non-stream, idempotent attribute setters (capture-safe)
    cudaFuncSetAttribute(k_scan, cudaFuncAttributeNonPortableClusterSizeAllowed, 1);
    cudaFuncSetAttribute(k_scan, cudaFuncAttributeMaxDynamicSharedMemorySize, SCAN_SMEM);

    dim3 gA(512, 48);
    k_inproj<<<gA, 256>>>(x, Wxf, Wxb);
    k_scan<<<NBLK, NTHR, SCAN_SMEM>>>(Whf, Whb, bf, bb, out);
}

// round 11
// speedup vs baseline: 3.1187x; 1.8771x over previous
#include <cuda_runtime.h>
#include <cuda_bf16.h>

typedef unsigned int u32;
typedef unsigned short u16;

#define B_   64
#define T_   512
#define D_   256
#define U_   512
#define G3   1536
#define NBLK 128
#define NTHR 512
#define SCAN_SMEM 181248   // 1KB align pad + A1/A2 128KB + W 32KB + V 16KB

// ---------------- device scratch (no allocations allowed) ----------------
__device__ float g_gx[(size_t)2 * T_ * B_ * G3];   // [dir][t][b][3U]
// bf16-split state images (ldmatrix-swizzled layout): [dir][64KB]
__device__ __align__(16) unsigned char g_h1[2][65536];
__device__ __align__(16) unsigned char g_h2[2][65536];
__device__ __align__(16) unsigned char g_r1[2][65536];
__device__ __align__(16) unsigned char g_r2[2][65536];
__device__ unsigned          g_barc[2] = {0, 0};
__device__ volatile unsigned g_barg[2] = {0, 0};

// Per-direction software barrier over 64 blocks (replay-safe, R2-proven).
__device__ __forceinline__ void dir_barrier(int dir) {
    __threadfence();
    __syncthreads();
    if (threadIdx.x == 0) {
        unsigned g = g_barg[dir];
        unsigned prev = atomicAdd(&g_barc[dir], 1u);
        if (prev == 63u) {
            g_barc[dir] = 0u;
            __threadfence();
            g_barg[dir] = g + 1u;
        } else {
            while (g_barg[dir] == g) { __nanosleep(32); }
        }
    }
    __syncthreads();
}

__device__ __forceinline__ float sigmoidf_(float z) {
    return 1.0f / (1.0f + __expf(-z));
}
__device__ __forceinline__ u32 smem_u32(const void* p) {
    u32 a;
    asm("{ .reg .u64 t; cvta.to.shared.u64 t, %1; cvt.u32.u64 %0, t; }"
        : "=r"(a) : "l"(p));
    return a;
}
// image layout: row (batch or weight-n) owns 1KB (512 bf16 along k);
// 16B chunks XOR-swizzled by row for conflict-free ldmatrix.
__device__ __forceinline__ u32 off_(u32 row, u32 k) {
    u32 c = k >> 3;
    c = (c & ~7u) | ((c ^ row) & 7u);
    return row * 1024u + c * 16u + (k & 7u) * 2u;
}
__device__ __forceinline__ void ldm4(u32* r, u32 addr) {
    asm volatile("ldmatrix.sync.aligned.m8n8.x4.shared.b16 {%0,%1,%2,%3}, [%4];"
        : "=r"(r[0]), "=r"(r[1]), "=r"(r[2]), "=r"(r[3]) : "r"(addr));
}
__device__ __forceinline__ void ldm2(u32* r, u32 addr) {
    asm volatile("ldmatrix.sync.aligned.m8n8.x2.shared.b16 {%0,%1}, [%2];"
        : "=r"(r[0]), "=r"(r[1]) : "r"(addr));
}
__device__ __forceinline__ void mma_bf16(float* d, const u32* a, const u32* b) {
    asm volatile("mma.sync.aligned.m16n8k16.row.col.f32.bf16.bf16.f32 "
        "{%0,%1,%2,%3}, {%4,%5,%6,%7}, {%8,%9}, {%0,%1,%2,%3};"
        : "+f"(d[0]), "+f"(d[1]), "+f"(d[2]), "+f"(d[3])
        : "r"(a[0]), "r"(a[1]), "r"(a[2]), "r"(a[3]), "r"(b[0]), "r"(b[1]));
}
__device__ __forceinline__ void split_bf16(float x, u16& hi, u16& lo) {
    __nv_bfloat16 h = __float2bfloat16(x);
    __nv_bfloat16 l = __float2bfloat16(x - __bfloat162float(h));
    hi = __bfloat16_as_ushort(h);
    lo = __bfloat16_as_ushort(l);
}
__device__ __forceinline__ float join_bf16(const void* p1, const void* p2) {
    return __bfloat162float(__ushort_as_bfloat16(*(const u16*)p1)) +
           __bfloat162float(__ushort_as_bfloat16(*(const u16*)p2));
}

// =====================================================================
// Kernel A: input projections for BOTH directions (fp32, R2-proven).
// =====================================================================
__global__ void __launch_bounds__(256) k_inproj(
    const float* __restrict__ x,
    const float* __restrict__ Wxf,
    const float* __restrict__ Wxb)
{
    __shared__ __align__(16) float As[16 * 64];
    __shared__ __align__(16) float Bs[16 * 64];

    const int tid = threadIdx.x;
    const int m0  = blockIdx.x * 64;
    const int n0g = blockIdx.y * 64;
    const int dir = (n0g >= G3) ? 1 : 0;
    const float* __restrict__ W = dir ? Wxb : Wxf;
    const int n0 = n0g - dir * G3;

    const int bg = tid >> 4;
    const int ng = tid & 15;
    const int ar = tid >> 2, aq = tid & 3;
    const int bk = tid >> 4, bc = tid & 15;

    float acc[4][4];
#pragma unroll
    for (int i = 0; i < 4; i++)
#pragma unroll
        for (int j = 0; j < 4; j++) acc[i][j] = 0.0f;

    for (int k0 = 0; k0 < D_; k0 += 16) {
        float4 av = *reinterpret_cast<const float4*>(x + (size_t)(m0 + ar) * D_ + k0 + aq * 4);
        float4 bv = *reinterpret_cast<const float4*>(W + (size_t)(k0 + bk) * G3 + n0 + bc * 4);
        __syncthreads();
        As[(aq * 4 + 0) * 64 + ar] = av.x;
        As[(aq * 4 + 1) * 64 + ar] = av.y;
        As[(aq * 4 + 2) * 64 + ar] = av.z;
        As[(aq * 4 + 3) * 64 + ar] = av.w;
        *reinterpret_cast<float4*>(&Bs[bk * 64 + bc * 4]) = bv;
        __syncthreads();
#pragma unroll
        for (int kk = 0; kk < 16; kk++) {
            float4 a4 = *reinterpret_cast<const float4*>(&As[kk * 64 + bg * 4]);
            float4 b4 = *reinterpret_cast<const float4*>(&Bs[kk * 64 + ng * 4]);
            float a[4] = {a4.x, a4.y, a4.z, a4.w};
            float b[4] = {b4.x, b4.y, b4.z, b4.w};
#pragma unroll
            for (int i = 0; i < 4; i++)
#pragma unroll
                for (int j = 0; j < 4; j++) acc[i][j] += a[i] * b[j];
        }
    }

#pragma unroll
    for (int i = 0; i < 4; i++) {
        int m = m0 + bg * 4 + i;
        int b = m >> 9;
        int s = m & 511;
        int t = dir ? (T_ - 1 - s) : s;
        float* dst = g_gx + (((size_t)dir * T_ + t) * B_ + b) * G3 + n0 + ng * 4;
        *reinterpret_cast<float4*>(dst) =
            make_float4(acc[i][0], acc[i][1], acc[i][2], acc[i][3]);
    }
}

// =====================================================================
// Kernel B: persistent HMMA (mma.sync bf16-split) scan.
// 128 blocks (64/dir), 512 thr. Block rank owns 8 u / 8 r / 8 cand cols.
// Phase A: warps 0-7 compute z=h@Wa (64x16), warps 8-15 extract hold.
// Phase B: warps 0-3 compute c=(r*h)@Wb (64x8).
// =====================================================================
extern __shared__ char dynsm[];

__global__ void __launch_bounds__(NTHR, 1)
k_scan(const float* __restrict__ Whf, const float* __restrict__ Whb,
       const float* __restrict__ bf,  const float* __restrict__ bb,
       float* __restrict__ out)
{
    __shared__ float sU[512];      // u gates  [b][8]
    __shared__ float sHold[512];   // h_old    [b][8] (block's cand cols)

    const int tid  = threadIdx.x;
    const int wid  = tid >> 5;
    const int lane = tid & 31;
    const int blk  = blockIdx.x;
    const int dir  = blk >> 6;
    const int rank = blk & 63;

    const float* __restrict__ Wh   = dir ? Whb : Whf;
    const float* __restrict__ bias = dir ? bb : bf;

    // 1KB-aligned dynamic smem regions
    const u32 raw  = smem_u32(dynsm);
    const u32 base = (raw + 1023u) & ~1023u;
    char* dp = dynsm + (base - raw);
    char* A1 = dp;                 // 64KB state hi
    char* A2 = dp + 65536;         // 64KB state lo
    char* W1 = dp + 131072;        // 16KB phase-A weights hi (16 rows x 512k)
    char* W2 = dp + 147456;        // 16KB phase-A weights lo
    char* V1 = dp + 163840;        //  8KB phase-B weights hi (8 rows x 512k)
    char* V2 = dp + 172032;        //  8KB phase-B weights lo
    const u32 A1u = base, A2u = base + 65536;
    const u32 W1u = base + 131072, W2u = base + 147456;
    const u32 V1u = base + 163840, V2u = base + 172032;

    // ---- split weight slices into smem (once per launch) ----
    for (int i = tid; i < 16 * 512; i += NTHR) {
        int n = i >> 9, k = i & 511;
        int col = (n < 8) ? (rank * 8 + n) : (512 + rank * 8 + (n - 8));
        u16 hi, lo;
        split_bf16(__ldg(Wh + (size_t)k * G3 + col), hi, lo);
        u32 o = off_((u32)n, (u32)k);
        *(u16*)(W1 + o) = hi;
        *(u16*)(W2 + o) = lo;
    }
    for (int i = tid; i < 8 * 512; i += NTHR) {
        int n = i >> 9, k = i & 511;
        int col = 1024 + rank * 8 + n;
        u16 hi, lo;
        split_bf16(__ldg(Wh + (size_t)k * G3 + col), hi, lo);
        u32 o = off_((u32)n, (u32)k);
        *(u16*)(V1 + o) = hi;
        *(u16*)(V2 + o) = lo;
    }

    // ---- ldmatrix lane mappings ----
    // Phase A (wid<8): mt = wid&3 (16 rows), nt = wid>>2 (8 cols)
    const int mt = wid & 3, nt = (wid >> 2) & 1;
    const u32 rA   = (u32)(mt * 16 + (lane & 15));
    const u32 khA  = (u32)(lane >> 4);
    const u32 aRow = rA * 1024u;
    const u32 rxA  = rA & 7u;
    const u32 nA   = (u32)(nt * 8 + (lane & 7));
    const u32 khB  = (u32)((lane >> 3) & 1);
    const u32 nRow = nA * 1024u;
    const u32 rxB  = nA & 7u;
    // Phase B (wid<4): mt = wid, 8 cols
    const u32 rB    = (u32)(wid * 16 + (lane & 15));
    const u32 bRow  = rB * 1024u;
    const u32 rxAB  = rB & 7u;
    const u32 nV    = (u32)(lane & 7);
    const u32 vRow  = nV * 1024u;
    const u32 rxV   = nV & 7u;

    // epilogue rows/cols
    const int er0 = mt * 16 + (lane >> 2);     // phase A (+8 for upper)
    const int ec0 = (lane & 3) * 2;            // col pair base (0..6)
    const int erB = wid * 16 + (lane >> 2);    // phase B rows

    // biases
    const int gbaseA = (nt ? 512 : 0) + rank * 8 + ec0;
    float2 biasA = make_float2(0.f, 0.f), biasC = make_float2(0.f, 0.f);
    if (wid < 8) biasA = *(const float2*)(bias + gbaseA);
    if (wid < 4) biasC = *(const float2*)(bias + 1024 + rank * 8 + ec0);

    const float* gx0 = g_gx + (size_t)dir * T_ * B_ * G3;

    for (int t = 0; t < T_; t++) {
        const float* gxt = gx0 + (size_t)t * B_ * G3;

        // ================= Phase A =================
        float2 gA0, gA1;
        if (wid < 8) {   // prefetch gx for epilogue (hides DRAM latency)
            const float* gp = gxt + (size_t)er0 * G3 + gbaseA;
            gA0 = __ldg((const float2*)gp);
            gA1 = __ldg((const float2*)(gp + (size_t)8 * G3));
        }
        // stage h split image -> A1/A2
        if (t == 0) {
            uint4 z0 = make_uint4(0, 0, 0, 0);
#pragma unroll
            for (int i = 0; i < 8; i++) {
                int idx = tid + i * NTHR;
                ((uint4*)A1)[idx] = z0;
                ((uint4*)A2)[idx] = z0;
            }
        } else {
            const uint4* s1 = (const uint4*)(g_h1[dir]);
            const uint4* s2 = (const uint4*)(g_h2[dir]);
#pragma unroll
            for (int i = 0; i < 8; i++) {
                int idx = tid + i * NTHR;
                ((uint4*)A1)[idx] = __ldcg(s1 + idx);
                ((uint4*)A2)[idx] = __ldcg(s2 + idx);
            }
        }
        __syncthreads();

        if (wid < 8) {
            float dhh[4] = {0, 0, 0, 0}, dhl[4] = {0, 0, 0, 0}, dlh[4] = {0, 0, 0, 0};
#pragma unroll 4
            for (int ks = 0; ks < 32; ks++) {
                u32 ca = (u32)(2 * ks) + khA;
                u32 cas = (ca & ~7u) | ((ca ^ rxA) & 7u);
                u32 aH[4], aL[4], bH[2], bL[2];
                ldm4(aH, A1u + aRow + cas * 16u);
                ldm4(aL, A2u + aRow + cas * 16u);
                u32 cb = (u32)(2 * ks) + khB;
                u32 cbs = (cb & ~7u) | ((cb ^ rxB) & 7u);
                ldm2(bH, W1u + nRow + cbs * 16u);
                ldm2(bL, W2u + nRow + cbs * 16u);
                mma_bf16(dhh, aH, bH);
                mma_bf16(dhl, aH, bL);
                mma_bf16(dlh, aL, bH);
            }
            float z0v = dhh[0] + dhl[0] + dlh[0];
            float z1v = dhh[1] + dhl[1] + dlh[1];
            float z2v = dhh[2] + dhl[2] + dlh[2];
            float z3v = dhh[3] + dhl[3] + dlh[3];

            if (nt == 0) {          // u gates -> sU
                sU[er0 * 8 + ec0]           = sigmoidf_(z0v + gA0.x + biasA.x);
                sU[er0 * 8 + ec0 + 1]       = sigmoidf_(z1v + gA0.y + biasA.y);
                sU[(er0 + 8) * 8 + ec0]     = sigmoidf_(z2v + gA1.x + biasA.x);
                sU[(er0 + 8) * 8 + ec0 + 1] = sigmoidf_(z3v + gA1.y + biasA.y);
            } else {                // r gates -> rh image
                float r0v = sigmoidf_(z0v + gA0.x + biasA.x);
                float r1v = sigmoidf_(z1v + gA0.y + biasA.y);
                float r2v = sigmoidf_(z2v + gA1.x + biasA.x);
                float r3v = sigmoidf_(z3v + gA1.y + biasA.y);
                u32 krh = (u32)(rank * 8 + ec0);
                u32 o0 = off_((u32)er0, krh);
                u32 o1 = off_((u32)(er0 + 8), krh);
                float h00 = join_bf16(A1 + o0, A2 + o0);
                float h01 = join_bf16(A1 + o0 + 2, A2 + o0 + 2);
                float h10 = join_bf16(A1 + o1, A2 + o1);
                float h11 = join_bf16(A1 + o1 + 2, A2 + o1 + 2);
                u16 a_hi, a_lo, b_hi, b_lo;
                split_bf16(r0v * h00, a_hi, a_lo);
                split_bf16(r1v * h01, b_hi, b_lo);
                *(u32*)(g_r1[dir] + o0) = (u32)a_hi | ((u32)b_hi << 16);
                *(u32*)(g_r2[dir] + o0) = (u32)a_lo | ((u32)b_lo << 16);
                split_bf16(r2v * h10, a_hi, a_lo);
                split_bf16(r3v * h11, b_hi, b_lo);
                *(u32*)(g_r1[dir] + o1) = (u32)a_hi | ((u32)b_hi << 16);
                *(u32*)(g_r2[dir] + o1) = (u32)a_lo | ((u32)b_lo << 16);
            }
        } else {
            // warps 8-15: extract hold for the block's cand cols
            int e = tid - 256;          // 0..255, elements e and e+256
#pragma unroll
            for (int q = 0; q < 2; q++) {
                int el = e + q * 256;
                int b = el >> 3, j = el & 7;
                u32 o = off_((u32)b, (u32)(rank * 8 + j));
                sHold[el] = join_bf16(A1 + o, A2 + o);
            }
        }
        dir_barrier(dir);

        // ================= Phase B =================
        float2 gC0, gC1;
        if (wid < 4) {
            const float* gp = gxt + (size_t)erB * G3 + 1024 + rank * 8 + ec0;
            gC0 = __ldg((const float2*)gp);
            gC1 = __ldg((const float2*)(gp + (size_t)8 * G3));
        }
        {
            const uint4* s1 = (const uint4*)(g_r1[dir]);
            const uint4* s2 = (const uint4*)(g_r2[dir]);
#pragma unroll
            for (int i = 0; i < 8; i++) {
                int idx = tid + i * NTHR;
                ((uint4*)A1)[idx] = __ldcg(s1 + idx);
                ((uint4*)A2)[idx] = __ldcg(s2 + idx);
            }
        }
        __syncthreads();

        if (wid < 4) {
            float dhh[4] = {0, 0, 0, 0}, dhl[4] = {0, 0, 0, 0}, dlh[4] = {0, 0, 0, 0};
#pragma unroll 4
            for (int ks = 0; ks < 32; ks++) {
                u32 ca = (u32)(2 * ks) + khA;
                u32 cas = (ca & ~7u) | ((ca ^ rxAB) & 7u);
                u32 aH[4], aL[4], bH[2], bL[2];
                ldm4(aH, A1u + bRow + cas * 16u);
                ldm4(aL, A2u + bRow + cas * 16u);
                u32 cb = (u32)(2 * ks) + khB;
                u32 cbs = (cb & ~7u) | ((cb ^ rxV) & 7u);
                ldm2(bH, V1u + vRow + cbs * 16u);
                ldm2(bL, V2u + vRow + cbs * 16u);
                mma_bf16(dhh, aH, bH);
                mma_bf16(dhl, aH, bL);
                mma_bf16(dlh, aL, bH);
            }
            float zv[4];
            zv[0] = dhh[0] + dhl[0] + dlh[0];
            zv[1] = dhh[1] + dhl[1] + dlh[1];
            zv[2] = dhh[2] + dhl[2] + dlh[2];
            zv[3] = dhh[3] + dhl[3] + dlh[3];

            float gcx[4] = {gC0.x, gC0.y, gC1.x, gC1.y};
            float bcx[4] = {biasC.x, biasC.y, biasC.x, biasC.y};
            u16 p_hi[4], p_lo[4];
            float hn[4];
#pragma unroll
            for (int q = 0; q < 4; q++) {
                int row = erB + (q >> 1) * 8;
                int col = ec0 + (q & 1);
                float hh   = tanhf(zv[q] + gcx[q] + bcx[q]);
                float uu   = sU[row * 8 + col];
                float hold = sHold[row * 8 + col];
                hn[q] = hold + uu * (hh - hold);
                split_bf16(hn[q], p_hi[q], p_lo[q]);
            }
            // output (fp32) + next-step h image
            float* op0 = out + ((size_t)erB * T_ + t) * 1024 + dir * 512 + rank * 8 + ec0;
            float* op1 = out + ((size_t)(erB + 8) * T_ + t) * 1024 + dir * 512 + rank * 8 + ec0;
            *(float2*)op0 = make_float2(hn[0], hn[1]);
            *(float2*)op1 = make_float2(hn[2], hn[3]);
            u32 kc = (u32)(rank * 8 + ec0);
            u32 o0 = off_((u32)erB, kc);
            u32 o1 = off_((u32)(erB + 8), kc);
            *(u32*)(g_h1[dir] + o0) = (u32)p_hi[0] | ((u32)p_hi[1] << 16);
            *(u32*)(g_h2[dir] + o0) = (u32)p_lo[0] | ((u32)p_lo[1] << 16);
            *(u32*)(g_h1[dir] + o1) = (u32)p_hi[2] | ((u32)p_hi[3] << 16);
            *(u32*)(g_h2[dir] + o1) = (u32)p_lo[2] | ((u32)p_lo[3] << 16);
        }
        dir_barrier(dir);
    }
}

// =====================================================================
extern "C" void kernel_launch(void* const* d_in, const int* in_sizes, int n_in,
                              void* d_out, int out_size)
{
    const float* x   = (const float*)d_in[0];
    const float* Wxf = (const float*)d_in[1];
    const float* Whf = (const float*)d_in[2];
    const float* bf  = (const float*)d_in[3];
    const float* Wxb = (const float*)d_in[4];
    const float* Whb = (const float*)d_in[5];
    const float* bb  = (const float*)d_in[6];
    float* out = (float*)d_out;

    cudaFuncSetAttribute(k_scan, cudaFuncAttributeMaxDynamicSharedMemorySize, SCAN_SMEM);

    dim3 gA(512, 48);
    k_inproj<<<gA, 256>>>(x, Wxf, Wxb);
    k_scan<<<NBLK, NTHR, SCAN_SMEM>>>(Whf, Whb, bf, bb, out);
}

// round 12
// speedup vs baseline: 3.9339x; 1.2614x over previous
#include <cuda_runtime.h>
#include <cuda_bf16.h>

typedef unsigned int u32;
typedef unsigned short u16;

#define B_   64
#define T_   512
#define D_   256
#define U_   512
#define G3   1536
#define NBLK 128
#define NTHR 512
#define SCAN_SMEM 181248
#define INPROJ_SMEM 98304

// ---------------- device scratch (no allocations allowed) ----------------
__device__ float g_gx[(size_t)2 * T_ * B_ * G3];   // [dir][t][b][3U]
// bf16-split state images (ldmatrix-swizzled): [dir][64KB]
__device__ __align__(16) unsigned char g_h1[2][65536];
__device__ __align__(16) unsigned char g_h2[2][65536];
__device__ __align__(16) unsigned char g_r1[2][65536];
__device__ __align__(16) unsigned char g_r2[2][65536];
// bf16-split inproj operand images
__device__ __align__(16) unsigned char g_x1[(size_t)32768 * 512];  // 16MB
__device__ __align__(16) unsigned char g_x2[(size_t)32768 * 512];
__device__ __align__(16) unsigned char g_w1[(size_t)3072 * 512];   // 1.5MB
__device__ __align__(16) unsigned char g_w2[(size_t)3072 * 512];
__device__ unsigned          g_barc[2] = {0, 0};
__device__ volatile unsigned g_barg[2] = {0, 0};

// Per-direction software barrier over 64 blocks (replay-safe; busy spin).
__device__ __forceinline__ void dir_barrier(int dir) {
    __threadfence();
    __syncthreads();
    if (threadIdx.x == 0) {
        unsigned g = g_barg[dir];
        unsigned prev = atomicAdd(&g_barc[dir], 1u);
        if (prev == 63u) {
            g_barc[dir] = 0u;
            __threadfence();
            g_barg[dir] = g + 1u;
        } else {
            while (g_barg[dir] == g) { }
        }
    }
    __syncthreads();
}

__device__ __forceinline__ float sigmoidf_(float z) {
    return 1.0f / (1.0f + __expf(-z));
}
__device__ __forceinline__ u32 smem_u32(const void* p) {
    u32 a;
    asm("{ .reg .u64 t; cvta.to.shared.u64 t, %1; cvt.u32.u64 %0, t; }"
        : "=r"(a) : "l"(p));
    return a;
}
// 1KB-row image offset (512 bf16/row), XOR swizzle on 16B chunks
__device__ __forceinline__ u32 off_(u32 row, u32 k) {
    u32 c = k >> 3;
    c = (c & ~7u) | ((c ^ row) & 7u);
    return row * 1024u + c * 16u + (k & 7u) * 2u;
}
// 512B-row image (256 bf16/row)
__device__ __host__ __forceinline__ u32 off512_(u32 row, u32 k) {
    u32 c = k >> 3;
    c = (c & ~7u) | ((c ^ row) & 7u);
    return row * 512u + c * 16u + (k & 7u) * 2u;
}
__device__ __forceinline__ void ldm4(u32* r, u32 addr) {
    asm volatile("ldmatrix.sync.aligned.m8n8.x4.shared.b16 {%0,%1,%2,%3}, [%4];"
        : "=r"(r[0]), "=r"(r[1]), "=r"(r[2]), "=r"(r[3]) : "r"(addr));
}
__device__ __forceinline__ void ldm2(u32* r, u32 addr) {
    asm volatile("ldmatrix.sync.aligned.m8n8.x2.shared.b16 {%0,%1}, [%2];"
        : "=r"(r[0]), "=r"(r[1]) : "r"(addr));
}
__device__ __forceinline__ void mma_bf16(float* d, const u32* a, const u32* b) {
    asm volatile("mma.sync.aligned.m16n8k16.row.col.f32.bf16.bf16.f32 "
        "{%0,%1,%2,%3}, {%4,%5,%6,%7}, {%8,%9}, {%0,%1,%2,%3};"
        : "+f"(d[0]), "+f"(d[1]), "+f"(d[2]), "+f"(d[3])
        : "r"(a[0]), "r"(a[1]), "r"(a[2]), "r"(a[3]), "r"(b[0]), "r"(b[1]));
}
__device__ __forceinline__ void split_bf16(float x, u16& hi, u16& lo) {
    __nv_bfloat16 h = __float2bfloat16(x);
    __nv_bfloat16 l = __float2bfloat16(x - __bfloat162float(h));
    hi = __bfloat16_as_ushort(h);
    lo = __bfloat16_as_ushort(l);
}
__device__ __forceinline__ float join_bf16(const void* p1, const void* p2) {
    return __bfloat162float(__ushort_as_bfloat16(*(const u16*)p1)) +
           __bfloat162float(__ushort_as_bfloat16(*(const u16*)p2));
}
#define CP16(dst, src) \
    asm volatile("cp.async.cg.shared.global [%0], [%1], 16;" :: "r"(dst), "l"(src) : "memory")
#define CP_COMMIT() asm volatile("cp.async.commit_group;" ::: "memory")
#define CP_WAIT0()  asm volatile("cp.async.wait_group 0;" ::: "memory")
#define CP_WAIT1()  asm volatile("cp.async.wait_group 1;" ::: "memory")

// =====================================================================
// Prep kernels: split x and [Wx_f | Wx_b] into bf16 hi/lo images.
// =====================================================================
__global__ void __launch_bounds__(256) k_split_x(const float* __restrict__ x)
{
    int idx = blockIdx.x * 256 + threadIdx.x;   // one 8-elem chunk
    int m = idx >> 5, c = idx & 31, k0 = c * 8;
    const float* src = x + (size_t)m * 256 + k0;
    float4 f0 = __ldg((const float4*)src);
    float4 f1 = __ldg((const float4*)(src + 4));
    float e[8] = {f0.x, f0.y, f0.z, f0.w, f1.x, f1.y, f1.z, f1.w};
    u16 h[8], l[8];
#pragma unroll
    for (int j = 0; j < 8; j++) split_bf16(e[j], h[j], l[j]);
    uint4 H = make_uint4(h[0] | (h[1] << 16), h[2] | (h[3] << 16),
                         h[4] | (h[5] << 16), h[6] | (h[7] << 16));
    uint4 L = make_uint4(l[0] | (l[1] << 16), l[2] | (l[3] << 16),
                         l[4] | (l[5] << 16), l[6] | (l[7] << 16));
    u32 o = off512_((u32)m, (u32)k0);
    *(uint4*)(g_x1 + o) = H;
    *(uint4*)(g_x2 + o) = L;
}

__global__ void __launch_bounds__(256) k_split_w(
    const float* __restrict__ Wxf, const float* __restrict__ Wxb)
{
    int n = blockIdx.x * 256 + threadIdx.x;    // 0..3071
    int dir = (n >= G3) ? 1 : 0;
    int col = n - dir * G3;
    const float* W = dir ? Wxb : Wxf;
    for (int c = 0; c < 32; c++) {
        u16 h[8], l[8];
#pragma unroll
        for (int j = 0; j < 8; j++)
            split_bf16(__ldg(W + (size_t)(c * 8 + j) * G3 + col), h[j], l[j]);
        uint4 H = make_uint4(h[0] | (h[1] << 16), h[2] | (h[3] << 16),
                             h[4] | (h[5] << 16), h[6] | (h[7] << 16));
        uint4 L = make_uint4(l[0] | (l[1] << 16), l[2] | (l[3] << 16),
                             l[4] | (l[5] << 16), l[6] | (l[7] << 16));
        u32 o = off512_((u32)n, (u32)(c * 8));
        *(uint4*)(g_w1 + o) = H;
        *(uint4*)(g_w2 + o) = L;
    }
}

// =====================================================================
// Kernel A: input projections via bf16-split HMMA.
// Tile M=128 (batch*time), N=64 (of 3072), K=256; 16 warps, each m32n16.
// cp.async double-buffered K=64 stages. Scatter epilogue into g_gx.
// =====================================================================
extern __shared__ char ipsm[];

__global__ void __launch_bounds__(NTHR, 1) k_inproj_mma(int dummy)
{
    const int tid  = threadIdx.x;
    const int wid  = tid >> 5;
    const int lane = tid & 31;
    const int m0   = blockIdx.x * 128;
    const int n0   = blockIdx.y * 64;
    const int wm   = wid & 3, wn = wid >> 2;

    const u32 sbase = smem_u32(ipsm);
    // stage s: Ah +0 (16K), Al +16K, Bh +32K (8K), Bl +40K
    auto stage_load = [&](int kt, int s) {
        u32 b0 = sbase + (u32)s * 49152u;
#pragma unroll
        for (int i = 0; i < 6; i++) {
            int gid = tid + i * NTHR;      // 0..3071
            if (gid < 2048) {
                int term = gid >> 10, row = (gid & 1023) >> 3, c = gid & 7;
                u32 dst = b0 + (u32)term * 16384u + (u32)(row * 128 + c * 16);
                const unsigned char* srcimg = term ? g_x2 : g_x1;
                CP16(dst, srcimg + (size_t)(m0 + row) * 512 + kt * 128 + c * 16);
            } else {
                int g2 = gid - 2048;
                int term = g2 >> 9, row = (g2 & 511) >> 3, c = g2 & 7;
                u32 dst = b0 + 32768u + (u32)term * 8192u + (u32)(row * 128 + c * 16);
                const unsigned char* srcimg = term ? g_w2 : g_w1;
                CP16(dst, srcimg + (size_t)(n0 + row) * 512 + kt * 128 + c * 16);
            }
        }
        CP_COMMIT();
    };

    float dhh[2][2][4], dlo[2][2][4];
#pragma unroll
    for (int mi = 0; mi < 2; mi++)
#pragma unroll
        for (int ni = 0; ni < 2; ni++)
#pragma unroll
            for (int q = 0; q < 4; q++) { dhh[mi][ni][q] = 0.f; dlo[mi][ni][q] = 0.f; }

    stage_load(0, 0);
    stage_load(1, 1);

    const u32 rA0 = (u32)(wm * 32 + (lane & 15));
    const u32 rA1 = rA0 + 16;
    const u32 nB0 = (u32)(wn * 16 + (lane & 7));
    const u32 nB1 = nB0 + 8;
    const u32 kq4 = (u32)(lane >> 4);          // ldm4 chunk sel
    const u32 kq2 = (u32)((lane >> 3) & 1);    // ldm2 chunk sel

    for (int kt = 0; kt < 4; kt++) {
        if (kt < 3) CP_WAIT1(); else CP_WAIT0();
        __syncthreads();
        u32 b0 = sbase + (u32)(kt & 1) * 49152u;
        u32 AhU = b0, AlU = b0 + 16384u, BhU = b0 + 32768u, BlU = b0 + 40960u;
#pragma unroll
        for (int ks = 0; ks < 4; ks++) {
            u32 ca = (u32)(2 * ks) + kq4;
            u32 ca0 = (ca ^ rA0) & 7u, ca1 = (ca ^ rA1) & 7u;
            u32 aH0[4], aH1[4], aL0[4], aL1[4];
            ldm4(aH0, AhU + rA0 * 128u + ca0 * 16u);
            ldm4(aH1, AhU + rA1 * 128u + ca1 * 16u);
            ldm4(aL0, AlU + rA0 * 128u + ca0 * 16u);
            ldm4(aL1, AlU + rA1 * 128u + ca1 * 16u);
            u32 cb = (u32)(2 * ks) + kq2;
            u32 cb0 = (cb ^ nB0) & 7u, cb1 = (cb ^ nB1) & 7u;
            u32 bH0[2], bH1[2], bL0[2], bL1[2];
            ldm2(bH0, BhU + nB0 * 128u + cb0 * 16u);
            ldm2(bH1, BhU + nB1 * 128u + cb1 * 16u);
            ldm2(bL0, BlU + nB0 * 128u + cb0 * 16u);
            ldm2(bL1, BlU + nB1 * 128u + cb1 * 16u);
            mma_bf16(dhh[0][0], aH0, bH0); mma_bf16(dhh[0][1], aH0, bH1);
            mma_bf16(dhh[1][0], aH1, bH0); mma_bf16(dhh[1][1], aH1, bH1);
            mma_bf16(dlo[0][0], aH0, bL0); mma_bf16(dlo[0][1], aH0, bL1);
            mma_bf16(dlo[1][0], aH1, bL0); mma_bf16(dlo[1][1], aH1, bL1);
            mma_bf16(dlo[0][0], aL0, bH0); mma_bf16(dlo[0][1], aL0, bH1);
            mma_bf16(dlo[1][0], aL1, bH0); mma_bf16(dlo[1][1], aL1, bH1);
        }
        __syncthreads();
        if (kt < 2) stage_load(kt + 2, kt & 1);
    }

    // scatter epilogue
#pragma unroll
    for (int mi = 0; mi < 2; mi++)
#pragma unroll
        for (int ni = 0; ni < 2; ni++) {
            int gm = m0 + wm * 32 + mi * 16 + (lane >> 2);
            int gc = n0 + wn * 16 + ni * 8 + (lane & 3) * 2;
            int dir = (gc >= G3) ? 1 : 0;
            int cc  = gc - dir * G3;
            int b   = gm >> 9;
#pragma unroll
            for (int half = 0; half < 2; half++) {
                int s = (gm + half * 8) & 511;
                int tt = dir ? (T_ - 1 - s) : s;
                float* d = g_gx + (((size_t)dir * T_ + tt) * B_ + b) * G3 + cc;
                *(float2*)d = make_float2(dhh[mi][ni][half * 2] + dlo[mi][ni][half * 2],
                                          dhh[mi][ni][half * 2 + 1] + dlo[mi][ni][half * 2 + 1]);
            }
        }
}

// =====================================================================
// Kernel B: persistent HMMA scan, K-split-2 warps, cp.async staging,
// u/h_old register-resident across phases. 128 blocks (64/dir), 512 thr.
// =====================================================================
extern __shared__ char dynsm[];

__global__ void __launch_bounds__(NTHR, 1)
k_scan(const float* __restrict__ Whf, const float* __restrict__ Whb,
       const float* __restrict__ bf,  const float* __restrict__ bb,
       float* __restrict__ out)
{
    __shared__ float sP[1024];     // cross-k-half partials (64x16)

    const int tid  = threadIdx.x;
    const int wid  = tid >> 5;
    const int lane = tid & 31;
    const int blk  = blockIdx.x;
    const int dir  = blk >> 6;
    const int rank = blk & 63;

    const float* __restrict__ Wh   = dir ? Whb : Whf;
    const float* __restrict__ bias = dir ? bb : bf;

    const u32 raw  = smem_u32(dynsm);
    const u32 base = (raw + 1023u) & ~1023u;
    char* dp = dynsm + (base - raw);
    char* A1 = dp;                 // 64KB state hi
    char* A2 = dp + 65536;         // 64KB state lo
    char* W1 = dp + 131072;        // 16KB phase-A weights hi (16 rows)
    char* W2 = dp + 147456;
    char* V1 = dp + 163840;        //  8KB phase-B weights hi (8 rows)
    char* V2 = dp + 172032;
    const u32 A1u = base, A2u = base + 65536;
    const u32 W1u = base + 131072, W2u = base + 147456;
    const u32 V1u = base + 163840, V2u = base + 172032;

    // ---- split weight slices into smem (once) ----
    for (int i = tid; i < 16 * 512; i += NTHR) {
        int n = i >> 9, k = i & 511;
        int col = (n < 8) ? (rank * 8 + n) : (512 + rank * 8 + (n - 8));
        u16 hi, lo;
        split_bf16(__ldg(Wh + (size_t)k * G3 + col), hi, lo);
        u32 o = off_((u32)n, (u32)k);
        *(u16*)(W1 + o) = hi;
        *(u16*)(W2 + o) = lo;
    }
    for (int i = tid; i < 8 * 512; i += NTHR) {
        int n = i >> 9, k = i & 511;
        u16 hi, lo;
        split_bf16(__ldg(Wh + (size_t)k * G3 + 1024 + rank * 8 + n), hi, lo);
        u32 o = off_((u32)n, (u32)k);
        *(u16*)(V1 + o) = hi;
        *(u16*)(V2 + o) = lo;
    }

    // ---- warp mappings ----
    // Phase A: 16 warps = 2 k-halves x (4m x 2n)
    const int khA = wid >> 3;
    const int ws  = wid & 7;
    const int mt  = ws & 3, nt = ws >> 2;
    const u32 rA   = (u32)(mt * 16 + (lane & 15));
    const u32 aRow = rA * 1024u;
    const u32 rxA  = rA & 7u;
    const u32 nA   = (u32)(nt * 8 + (lane & 7));
    const u32 nRow = nA * 1024u;
    const u32 rxB  = nA & 7u;
    const u32 kq4  = (u32)(lane >> 4);
    const u32 kq2  = (u32)((lane >> 3) & 1);
    // Phase B: warps 0-7 = 2 k-halves x 4m
    const int khB = (wid >> 2) & 1;
    const int mtB = wid & 3;
    const u32 rB   = (u32)(mtB * 16 + (lane & 15));
    const u32 bRow = rB * 1024u;
    const u32 rxAB = rB & 7u;
    const u32 nV   = (u32)(lane & 7);
    const u32 vRow = nV * 1024u;
    const u32 rxV  = nV & 7u;

    // epilogue rows/cols
    const int er0 = mt * 16 + (lane >> 2);      // phase A rows (+8)
    const int ec0 = (lane & 3) * 2;
    const int erB = mtB * 16 + (lane >> 2);     // phase B rows (+8)

    const int gbaseA = (nt ? 512 : 0) + rank * 8 + ec0;
    float2 biasA = make_float2(0.f, 0.f), biasC = make_float2(0.f, 0.f);
    if (wid < 8) biasA = *(const float2*)(bias + gbaseA);
    if (wid < 4) biasC = *(const float2*)(bias + 1024 + rank * 8 + ec0);

    float ureg[4], holdreg[4];
    const float* gx0 = g_gx + (size_t)dir * T_ * B_ * G3;

    for (int t = 0; t < T_; t++) {
        const float* gxt = gx0 + (size_t)t * B_ * G3;

        // ================= Phase A =================
        float2 gA0, gA1;
        if (wid < 8) {
            const float* gp = gxt + (size_t)er0 * G3 + gbaseA;
            gA0 = __ldg((const float2*)gp);
            gA1 = __ldg((const float2*)(gp + (size_t)8 * G3));
        }
        if (t == 0) {
            uint4 z0 = make_uint4(0, 0, 0, 0);
#pragma unroll
            for (int i = 0; i < 8; i++) {
                int idx = tid + i * NTHR;
                ((uint4*)A1)[idx] = z0;
                ((uint4*)A2)[idx] = z0;
            }
        } else {
#pragma unroll
            for (int i = 0; i < 8; i++) {
                u32 ch = (u32)(tid + i * NTHR) * 16u;
                CP16(A1u + ch, g_h1[dir] + ch);
                CP16(A2u + ch, g_h2[dir] + ch);
            }
            CP_COMMIT();
            CP_WAIT0();
        }
        __syncthreads();

        if (wid < 4) {   // hold extraction for phase-B blend (same thread)
            u32 kc = (u32)(rank * 8 + ec0);
            u32 o0 = off_((u32)er0, kc), o1 = off_((u32)(er0 + 8), kc);
            holdreg[0] = join_bf16(A1 + o0, A2 + o0);
            holdreg[1] = join_bf16(A1 + o0 + 2, A2 + o0 + 2);
            holdreg[2] = join_bf16(A1 + o1, A2 + o1);
            holdreg[3] = join_bf16(A1 + o1 + 2, A2 + o1 + 2);
        }

        {
            float dhh[4] = {0, 0, 0, 0}, dlo[4] = {0, 0, 0, 0};
#pragma unroll 4
            for (int ks = 0; ks < 16; ks++) {
                int kk = khA * 16 + ks;
                u32 ca = (u32)(2 * kk) + kq4;
                u32 cas = (ca & ~7u) | ((ca ^ rxA) & 7u);
                u32 aH[4], aL[4], bH[2], bL[2];
                ldm4(aH, A1u + aRow + cas * 16u);
                ldm4(aL, A2u + aRow + cas * 16u);
                u32 cb = (u32)(2 * kk) + kq2;
                u32 cbs = (cb & ~7u) | ((cb ^ rxB) & 7u);
                ldm2(bH, W1u + nRow + cbs * 16u);
                ldm2(bL, W2u + nRow + cbs * 16u);
                mma_bf16(dhh, aH, bH);
                mma_bf16(dlo, aH, bL);
                mma_bf16(dlo, aL, bH);
            }
            if (khA == 1) {   // store partials
                sP[er0 * 16 + nt * 8 + ec0]           = dhh[0] + dlo[0];
                sP[er0 * 16 + nt * 8 + ec0 + 1]       = dhh[1] + dlo[1];
                sP[(er0 + 8) * 16 + nt * 8 + ec0]     = dhh[2] + dlo[2];
                sP[(er0 + 8) * 16 + nt * 8 + ec0 + 1] = dhh[3] + dlo[3];
            }
            __syncthreads();
            if (khA == 0) {
                float z0v = dhh[0] + dlo[0] + sP[er0 * 16 + nt * 8 + ec0];
                float z1v = dhh[1] + dlo[1] + sP[er0 * 16 + nt * 8 + ec0 + 1];
                float z2v = dhh[2] + dlo[2] + sP[(er0 + 8) * 16 + nt * 8 + ec0];
                float z3v = dhh[3] + dlo[3] + sP[(er0 + 8) * 16 + nt * 8 + ec0 + 1];
                if (nt == 0) {       // u gates -> registers (phase-B consumer = me)
                    ureg[0] = sigmoidf_(z0v + gA0.x + biasA.x);
                    ureg[1] = sigmoidf_(z1v + gA0.y + biasA.y);
                    ureg[2] = sigmoidf_(z2v + gA1.x + biasA.x);
                    ureg[3] = sigmoidf_(z3v + gA1.y + biasA.y);
                } else {             // r gates -> rh image
                    float r0v = sigmoidf_(z0v + gA0.x + biasA.x);
                    float r1v = sigmoidf_(z1v + gA0.y + biasA.y);
                    float r2v = sigmoidf_(z2v + gA1.x + biasA.x);
                    float r3v = sigmoidf_(z3v + gA1.y + biasA.y);
                    u32 krh = (u32)(rank * 8 + ec0);
                    u32 o0 = off_((u32)er0, krh);
                    u32 o1 = off_((u32)(er0 + 8), krh);
                    float h00 = join_bf16(A1 + o0, A2 + o0);
                    float h01 = join_bf16(A1 + o0 + 2, A2 + o0 + 2);
                    float h10 = join_bf16(A1 + o1, A2 + o1);
                    float h11 = join_bf16(A1 + o1 + 2, A2 + o1 + 2);
                    u16 a_hi, a_lo, b_hi, b_lo;
                    split_bf16(r0v * h00, a_hi, a_lo);
                    split_bf16(r1v * h01, b_hi, b_lo);
                    *(u32*)(g_r1[dir] + o0) = (u32)a_hi | ((u32)b_hi << 16);
                    *(u32*)(g_r2[dir] + o0) = (u32)a_lo | ((u32)b_lo << 16);
                    split_bf16(r2v * h10, a_hi, a_lo);
                    split_bf16(r3v * h11, b_hi, b_lo);
                    *(u32*)(g_r1[dir] + o1) = (u32)a_hi | ((u32)b_hi << 16);
                    *(u32*)(g_r2[dir] + o1) = (u32)a_lo | ((u32)b_lo << 16);
                }
            }
        }
        dir_barrier(dir);

        // ================= Phase B =================
        float2 gC0, gC1;
        if (wid < 4) {
            const float* gp = gxt + (size_t)erB * G3 + 1024 + rank * 8 + ec0;
            gC0 = __ldg((const float2*)gp);
            gC1 = __ldg((const float2*)(gp + (size_t)8 * G3));
        }
#pragma unroll
        for (int i = 0; i < 8; i++) {
            u32 ch = (u32)(tid + i * NTHR) * 16u;
            CP16(A1u + ch, g_r1[dir] + ch);
            CP16(A2u + ch, g_r2[dir] + ch);
        }
        CP_COMMIT();
        CP_WAIT0();
        __syncthreads();

        if (wid < 8) {
            float dhh[4] = {0, 0, 0, 0}, dlo[4] = {0, 0, 0, 0};
#pragma unroll 4
            for (int ks = 0; ks < 16; ks++) {
                int kk = khB * 16 + ks;
                u32 ca = (u32)(2 * kk) + kq4;
                u32 cas = (ca & ~7u) | ((ca ^ rxAB) & 7u);
                u32 aH[4], aL[4], bH[2], bL[2];
                ldm4(aH, A1u + bRow + cas * 16u);
                ldm4(aL, A2u + bRow + cas * 16u);
                u32 cb = (u32)(2 * kk) + kq2;
                u32 cbs = (cb & ~7u) | ((cb ^ rxV) & 7u);
                ldm2(bH, V1u + vRow + cbs * 16u);
                ldm2(bL, V2u + vRow + cbs * 16u);
                mma_bf16(dhh, aH, bH);
                mma_bf16(dlo, aH, bL);
                mma_bf16(dlo, aL, bH);
            }
            if (khB == 1) {
                sP[erB * 8 + ec0]           = dhh[0] + dlo[0];
                sP[erB * 8 + ec0 + 1]       = dhh[1] + dlo[1];
                sP[(erB + 8) * 8 + ec0]     = dhh[2] + dlo[2];
                sP[(erB + 8) * 8 + ec0 + 1] = dhh[3] + dlo[3];
            }
            __syncthreads();
            if (khB == 0) {
                float zv[4];
                zv[0] = dhh[0] + dlo[0] + sP[erB * 8 + ec0];
                zv[1] = dhh[1] + dlo[1] + sP[erB * 8 + ec0 + 1];
                zv[2] = dhh[2] + dlo[2] + sP[(erB + 8) * 8 + ec0];
                zv[3] = dhh[3] + dlo[3] + sP[(erB + 8) * 8 + ec0 + 1];
                float gcx[4] = {gC0.x, gC0.y, gC1.x, gC1.y};
                float bcx[4] = {biasC.x, biasC.y, biasC.x, biasC.y};
                u16 p_hi[4], p_lo[4];
                float hn[4];
#pragma unroll
                for (int q = 0; q < 4; q++) {
                    float hh = tanhf(zv[q] + gcx[q] + bcx[q]);
                    hn[q] = holdreg[q] + ureg[q] * (hh - holdreg[q]);
                    split_bf16(hn[q], p_hi[q], p_lo[q]);
                }
                float* op0 = out + ((size_t)erB * T_ + t) * 1024 + dir * 512 + rank * 8 + ec0;
                float* op1 = out + ((size_t)(erB + 8) * T_ + t) * 1024 + dir * 512 + rank * 8 + ec0;
                *(float2*)op0 = make_float2(hn[0], hn[1]);
                *(float2*)op1 = make_float2(hn[2], hn[3]);
                u32 kc = (u32)(rank * 8 + ec0);
                u32 o0 = off_((u32)erB, kc);
                u32 o1 = off_((u32)(erB + 8), kc);
                *(u32*)(g_h1[dir] + o0) = (u32)p_hi[0] | ((u32)p_hi[1] << 16);
                *(u32*)(g_h2[dir] + o0) = (u32)p_lo[0] | ((u32)p_lo[1] << 16);
                *(u32*)(g_h1[dir] + o1) = (u32)p_hi[2] | ((u32)p_hi[3] << 16);
                *(u32*)(g_h2[dir] + o1) = (u32)p_lo[2] | ((u32)p_lo[3] << 16);
            }
        } else {
            __syncthreads();   // match khB partial sync
        }
        dir_barrier(dir);
    }
}

// =====================================================================
extern "C" void kernel_launch(void* const* d_in, const int* in_sizes, int n_in,
                              void* d_out, int out_size)
{
    const float* x   = (const float*)d_in[0];
    const float* Wxf = (const float*)d_in[1];
    const float* Whf = (const float*)d_in[2];
    const float* bf  = (const float*)d_in[3];
    const float* Wxb = (const float*)d_in[4];
    const float* Whb = (const float*)d_in[5];
    const float* bb  = (const float*)d_in[6];
    float* out = (float*)d_out;

    cudaFuncSetAttribute(k_scan, cudaFuncAttributeMaxDynamicSharedMemorySize, SCAN_SMEM);
    cudaFuncSetAttribute(k_inproj_mma, cudaFuncAttributeMaxDynamicSharedMemorySize, INPROJ_SMEM);

    k_split_x<<<4096, 256>>>(x);
    k_split_w<<<12, 256>>>(Wxf, Wxb);
    dim3 gI(256, 48);
    k_inproj_mma<<<gI, NTHR, INPROJ_SMEM>>>(0);
    k_scan<<<NBLK, NTHR, SCAN_SMEM>>>(Whf, Whb, bf, bb, out);
}